// round 14
// baseline (speedup 1.0000x reference)
#include <cuda_runtime.h>
#include <cuda_bf16.h>
#include <cstdint>

// Problem constants
#define NN 200000
#define D  128
#define P  4096
#define R  4
#define T  3
#define K  16

// ---------------------------------------------------------------------------
// Scratch (static __device__ — no runtime allocation)
// ---------------------------------------------------------------------------
__device__ __align__(16) float g_u[T * D];          // u_t = W_phi[t] @ zn
__device__ __align__(16) float g_v[T * D];          // v_t = W_phi[t] @ zs
__device__ __align__(16) float g_bias2[D];          // 2 * sum_r W_beta_b[r][e]
__device__ __align__(16) float g_y1[NN];            // x[n] . u_{ty[n]}
__device__ __align__(16) float g_y2[NN];            // x[n] . v_{ty[n]}
// G matrix in bf16: row p has 256 uints (512 bf16 = R*D k-values)
__device__ __align__(16) uint32_t g_gb[P * R * 64];
// Packed bf16 B fragments for m16n8k16: entry idx = (kt*4+t)*128 + n.
// .x = {B[kt*16+2t][n], B[kt*16+2t+1][n]}, .y = same with k+8.
__device__ __align__(16) uint2 g_wbQ[128 * 128];

// ---------------------------------------------------------------------------
// Kernel 1: setup — fused wbq pack (blocks 0..63), u/v prep (64..66),
// bias2 (67). grid=68 x 256.
// ---------------------------------------------------------------------------
__global__ void setup_kernel(const float* __restrict__ W_phi,
                             const float* __restrict__ W_zeta,
                             const float* __restrict__ W_beta_b,
                             const float* __restrict__ Wb) {
    int b = blockIdx.x;
    int tid = threadIdx.x;
    if (b < 64) {
        int idx = b * 256 + tid;   // row*128 + n
        int row = idx >> 7;        // kt*4 + t
        int n = idx & 127;
        int kt = row >> 2, t = row & 3;
        int k0 = kt * 16 + t * 2;
        float w00 = Wb[k0 * D + n];
        float w01 = Wb[(k0 + 1) * D + n];
        float w10 = Wb[(k0 + 8) * D + n];
        float w11 = Wb[(k0 + 9) * D + n];
        uint32_t b0, b1;
        asm("cvt.rn.bf16x2.f32 %0, %1, %2;" : "=r"(b0) : "f"(w01), "f"(w00));
        asm("cvt.rn.bf16x2.f32 %0, %1, %2;" : "=r"(b1) : "f"(w11), "f"(w10));
        g_wbQ[idx] = make_uint2(b0, b1);
    } else if (b < 67) {
        if (tid < D) {
            int ty = b - 64;
            const float* wrow = W_phi + (ty * D + tid) * D;
            float au = 0.f, av = 0.f;
#pragma unroll 8
            for (int e = 0; e < D; e++) {
                float w = wrow[e];
                au = fmaf(w, W_zeta[e], au);
                av = fmaf(w, W_zeta[D + e], av);
            }
            g_u[ty * D + tid] = au;
            g_v[ty * D + tid] = av;
        }
    } else {
        if (tid < D) {
            float s = 0.f;
#pragma unroll
            for (int r = 0; r < R; r++) s += W_beta_b[r * D + tid];
            g_bias2[tid] = 2.f * s;
        }
    }
}

// ---------------------------------------------------------------------------
// Kernel 2: ypass — per-node dots y1 = x.u_ty, y2 = x.v_ty, all 200k nodes.
// Warp per node, coalesced 512B row reads. grid = 25000 x 256.
// ---------------------------------------------------------------------------
__global__ __launch_bounds__(256) void ypass_kernel(
    const float* __restrict__ x,
    const int* __restrict__ types) {

    int lane = threadIdx.x & 31;
    int node = blockIdx.x * 8 + (threadIdx.x >> 5);
    int ty = types[node];
    float4 xr = *(const float4*)(x + (size_t)node * D + lane * 4);
    float4 u4 = *(const float4*)(g_u + ty * D + lane * 4);
    float4 v4 = *(const float4*)(g_v + ty * D + lane * 4);
    float d = xr.x * u4.x + xr.y * u4.y + xr.z * u4.z + xr.w * u4.w;
    float e = xr.x * v4.x + xr.y * v4.y + xr.z * v4.z + xr.w * v4.w;
#pragma unroll
    for (int off = 16; off; off >>= 1) {
        d += __shfl_xor_sync(0xffffffffu, d, off);
        e += __shfl_xor_sync(0xffffffffu, e, off);
    }
    if (lane == 0) {
        g_y1[node] = d;
        g_y2[node] = e;
    }
}

// ---------------------------------------------------------------------------
// Kernel 3: main — gather + softmax + aggregate. Block = pair p (128 thr),
// warp w = relation r. e_n from precomputed y1 (no dot, no butterfly, no
// smem u-table), deferred softmax normalization. Writes G as bf16.
// grid = 4096.
// ---------------------------------------------------------------------------
__global__ __launch_bounds__(128) void main_kernel(
    const float* __restrict__ x,
    const int* __restrict__ pairs,
    const int* __restrict__ nbr,
    const float* __restrict__ dt) {

    int p = blockIdx.x;
    int w = threadIdx.x >> 5;    // r
    int lane = threadIdx.x & 31;

    int base0 = (p * 2 * R + w) * K;
    int base1 = base0 + R * K;

    float es0 = g_y2[pairs[2 * p]];
    float es1 = g_y2[pairs[2 * p + 1]];

    int ni0 = 0, ni1 = 0;
    float ex0 = 0.f, ex1 = 0.f;
    if (lane < 16) {
        ni0 = nbr[base0 + lane];
        ni1 = nbr[base1 + lane];
        float edt0 = __expf(-dt[base0 + lane]);
        float edt1 = __expf(-dt[base1 + lane]);
        ex0 = __expf((g_y1[ni0] + es0) * edt0);
        ex1 = __expf((g_y1[ni1] + es1) * edt1);
    }

    float4 hacc = make_float4(0.f, 0.f, 0.f, 0.f);

#pragma unroll
    for (int s = 0; s < 2; s++) {
        int   ni = s ? ni1 : ni0;
        float ex = s ? ex1 : ex0;

        float sum = 0.f;
        float4 hs = make_float4(0.f, 0.f, 0.f, 0.f);

#pragma unroll
        for (int b = 0; b < 2; b++) {        // two batches of 8 neighbors
            float4 xv[8];
#pragma unroll
            for (int j = 0; j < 8; j++) {
                int nik = __shfl_sync(0xffffffffu, ni, b * 8 + j);
                xv[j] = *(const float4*)(x + (size_t)nik * D + lane * 4);
            }
#pragma unroll
            for (int j = 0; j < 8; j++) {
                float exk = __shfl_sync(0xffffffffu, ex, b * 8 + j);
                sum += exk;
                hs.x = fmaf(exk, xv[j].x, hs.x);
                hs.y = fmaf(exk, xv[j].y, hs.y);
                hs.z = fmaf(exk, xv[j].z, hs.z);
                hs.w = fmaf(exk, xv[j].w, hs.w);
            }
        }
        float inv = __fdividef(1.f, sum);
        hacc.x = fmaf(inv, hs.x, hacc.x);
        hacc.y = fmaf(inv, hs.y, hacc.y);
        hacc.z = fmaf(inv, hs.z, hacc.z);
        hacc.w = fmaf(inv, hs.w, hacc.w);
    }

    // store as bf16x2 pair (rounded to bf16 anyway in the MMA)
    uint32_t c0, c1;
    asm("cvt.rn.bf16x2.f32 %0, %1, %2;" : "=r"(c0) : "f"(hacc.y), "f"(hacc.x));
    asm("cvt.rn.bf16x2.f32 %0, %1, %2;" : "=r"(c1) : "f"(hacc.w), "f"(hacc.z));
    *(uint2*)(g_gb + (size_t)(p * R + w) * 64 + lane * 2) = make_uint2(c0, c1);
}

// ---------------------------------------------------------------------------
// Kernel 4: warp-level bf16 tensor-core out-GEMM + fused epilogue.
// C[4096,128] = G @ Wb; out = sigmoid(0.125*(C + bias2)).
// 128 CTAs x 256 thr (8 warps = 2 M-strips x 4 N-quarters). No smem:
// B fragments via __ldg (128 KB, L1-resident per SM, shared across warps);
// A as LDG.32 bf16x2 from g_gb. kt-loop unrolled x2 for MLP.
// ---------------------------------------------------------------------------
__global__ __launch_bounds__(256) void mma_out_kernel(float* __restrict__ out) {
    int tid = threadIdx.x;
    int w = tid >> 5;
    int ms = w >> 2;          // 0..1  (16-row strip)
    int nh = w & 3;           // 0..3  (32-col quarter)
    int lane = tid & 31;
    int g = lane >> 2;
    int t = lane & 3;

    int rm0 = blockIdx.x * 32 + ms * 16 + g;
    const uint32_t* ga0 = g_gb + (size_t)rm0 * 256 + t;
    const uint32_t* ga1 = ga0 + 8 * 256;

    float acc[4][4];
#pragma unroll
    for (int j = 0; j < 4; j++)
#pragma unroll
        for (int i = 0; i < 4; i++) acc[j][i] = 0.f;

#pragma unroll 2
    for (int kt = 0; kt < 32; kt++) {
        uint32_t a0 = __ldg(ga0 + kt * 8);
        uint32_t a1 = __ldg(ga1 + kt * 8);
        uint32_t a2 = __ldg(ga0 + kt * 8 + 4);
        uint32_t a3 = __ldg(ga1 + kt * 8 + 4);
        const uint2* brow = g_wbQ + (kt * 4 + t) * 128 + nh * 32 + g;
        uint2 bq0 = __ldg(brow);
        uint2 bq1 = __ldg(brow + 8);
        uint2 bq2 = __ldg(brow + 16);
        uint2 bq3 = __ldg(brow + 24);
#define DO_MMA(j, bq) \
        asm volatile( \
            "mma.sync.aligned.m16n8k16.row.col.f32.bf16.bf16.f32 " \
            "{%0,%1,%2,%3}, {%4,%5,%6,%7}, {%8,%9}, {%0,%1,%2,%3};" \
            : "+f"(acc[j][0]), "+f"(acc[j][1]), "+f"(acc[j][2]), "+f"(acc[j][3]) \
            : "r"(a0), "r"(a1), "r"(a2), "r"(a3), "r"(bq.x), "r"(bq.y))
        DO_MMA(0, bq0);
        DO_MMA(1, bq1);
        DO_MMA(2, bq2);
        DO_MMA(3, bq3);
#undef DO_MMA
    }

    // epilogue: bias + 0.125 scale + sigmoid, direct to out
    float* orow0 = out + (size_t)rm0 * D;
    float* orow1 = orow0 + 8 * D;
#pragma unroll
    for (int j = 0; j < 4; j++) {
        int n0 = (nh * 4 + j) * 8 + t * 2;
        float b0v = g_bias2[n0];
        float b1v = g_bias2[n0 + 1];
        float v00 = 0.125f * (acc[j][0] + b0v);
        float v01 = 0.125f * (acc[j][1] + b1v);
        float v10 = 0.125f * (acc[j][2] + b0v);
        float v11 = 0.125f * (acc[j][3] + b1v);
        float2 o0, o1;
        o0.x = __fdividef(1.f, 1.f + __expf(-v00));
        o0.y = __fdividef(1.f, 1.f + __expf(-v01));
        o1.x = __fdividef(1.f, 1.f + __expf(-v10));
        o1.y = __fdividef(1.f, 1.f + __expf(-v11));
        *(float2*)(orow0 + n0) = o0;
        *(float2*)(orow1 + n0) = o1;
    }
}

// ---------------------------------------------------------------------------
// Launch
// ---------------------------------------------------------------------------
extern "C" void kernel_launch(void* const* d_in, const int* in_sizes, int n_in,
                              void* d_out, int out_size) {
    const float* node_embeds   = (const float*)d_in[0];
    const int*   node_pairs    = (const int*)d_in[1];
    const int*   node_type_ids = (const int*)d_in[2];
    const int*   neighbor_idx  = (const int*)d_in[3];
    const float* delta_t       = (const float*)d_in[4];
    const float* W_phi         = (const float*)d_in[5];
    const float* W_zeta        = (const float*)d_in[6];
    const float* W_beta_w      = (const float*)d_in[7];
    const float* W_beta_b      = (const float*)d_in[8];
    float* out = (float*)d_out;

    setup_kernel<<<68, 256>>>(W_phi, W_zeta, W_beta_b, W_beta_w);
    ypass_kernel<<<NN / 8, 256>>>(node_embeds, node_type_ids);
    main_kernel<<<P, 128>>>(node_embeds, node_pairs, neighbor_idx, delta_t);
    mma_out_kernel<<<P / 32, 256>>>(out);
}

// round 15
// speedup vs baseline: 1.2889x; 1.2889x over previous
#include <cuda_runtime.h>
#include <cuda_bf16.h>
#include <cstdint>

// Problem constants
#define NN 200000
#define D  128
#define P  4096
#define R  4
#define T  3
#define K  16

// ---------------------------------------------------------------------------
// Scratch (static __device__ — no runtime allocation)
// ---------------------------------------------------------------------------
__device__ __align__(16) float g_u[T * D];          // u_t = W_phi[t] @ zn
__device__ __align__(16) float g_v[T * D];          // v_t = W_phi[t] @ zs
__device__ __align__(16) float g_bias2[D];          // 0.25 * sum_r W_beta_b[r][e]
__device__ __align__(16) float g_es[P * 2];         // e_s per (p,s)
// G matrix in bf16: row p has 256 uints (512 bf16 = R*D k-values)
__device__ __align__(16) uint32_t g_gb[P * 256];
// Packed bf16 B fragments (0.125*Wb) for m16n8k16: idx = (kt*4+t)*128 + n.
// .x = {B[kt*16+2t][n], B[kt*16+2t+1][n]}, .y = same with k+8.
__device__ __align__(16) uint2 g_wbQ[128 * 128];

// ---------------------------------------------------------------------------
// Kernel 1: setup — fused wbq pack (blocks 0..63, with 0.125 prescale),
// u/v prep (64..66), bias2 (67). grid=68 x 256.
// ---------------------------------------------------------------------------
__global__ void setup_kernel(const float* __restrict__ W_phi,
                             const float* __restrict__ W_zeta,
                             const float* __restrict__ W_beta_b,
                             const float* __restrict__ Wb) {
    int b = blockIdx.x;
    int tid = threadIdx.x;
    if (b < 64) {
        int idx = b * 256 + tid;   // row*128 + n
        int row = idx >> 7;        // kt*4 + t
        int n = idx & 127;
        int kt = row >> 2, t = row & 3;
        int k0 = kt * 16 + t * 2;
        float w00 = 0.125f * Wb[k0 * D + n];
        float w01 = 0.125f * Wb[(k0 + 1) * D + n];
        float w10 = 0.125f * Wb[(k0 + 8) * D + n];
        float w11 = 0.125f * Wb[(k0 + 9) * D + n];
        uint32_t b0, b1;
        asm("cvt.rn.bf16x2.f32 %0, %1, %2;" : "=r"(b0) : "f"(w01), "f"(w00));
        asm("cvt.rn.bf16x2.f32 %0, %1, %2;" : "=r"(b1) : "f"(w11), "f"(w10));
        g_wbQ[idx] = make_uint2(b0, b1);
    } else if (b < 67) {
        if (tid < D) {
            int ty = b - 64;
            const float* wrow = W_phi + (ty * D + tid) * D;
            float au = 0.f, av = 0.f;
#pragma unroll 8
            for (int e = 0; e < D; e++) {
                float w = wrow[e];
                au = fmaf(w, W_zeta[e], au);
                av = fmaf(w, W_zeta[D + e], av);
            }
            g_u[ty * D + tid] = au;
            g_v[ty * D + tid] = av;
        }
    } else {
        if (tid < D) {
            float s = 0.f;
#pragma unroll
            for (int r = 0; r < R; r++) s += W_beta_b[r * D + tid];
            g_bias2[tid] = 0.25f * s;
        }
    }
}

// ---------------------------------------------------------------------------
// Kernel 2: e_s per (p,s). One warp per pair-slot. grid=2048 x 128.
// ---------------------------------------------------------------------------
__global__ void es_kernel(const float* __restrict__ x,
                          const int* __restrict__ node_pairs,
                          const int* __restrict__ types) {
    int tid = threadIdx.x;
    int lane = tid & 31;
    int gw = blockIdx.x * 4 + (tid >> 5);   // ps index, 0..8191
    int node = node_pairs[gw];
    int t = types[node];
    const float4 x4 = *(const float4*)(x + (size_t)node * D + lane * 4);
    const float4 v4 = *(const float4*)(g_v + t * D + lane * 4);
    float part = x4.x * v4.x + x4.y * v4.y + x4.z * v4.z + x4.w * v4.w;
#pragma unroll
    for (int off = 16; off; off >>= 1)
        part += __shfl_xor_sync(0xffffffffu, part, off);
    if (lane == 0) g_es[gw] = part;
}

// ---------------------------------------------------------------------------
// Kernel 3: main — gather + softmax + aggregate (R12 butterfly structure —
// measured 38.4us; the ypass variant costs an extra DRAM sweep of x).
// Block = pair p (128 thr), warp w = relation r. Writes G as bf16.
// ---------------------------------------------------------------------------
__global__ __launch_bounds__(128) void main_kernel(
    const float* __restrict__ x,
    const int* __restrict__ types,
    const int* __restrict__ nbr,
    const float* __restrict__ dt) {

    int p = blockIdx.x;
    int tid = threadIdx.x;
    int w = tid >> 5;       // r
    int lane = tid & 31;

    __shared__ __align__(16) float s_u[T * D];   // 1.5 KB
    s_u[tid]       = g_u[tid];
    s_u[tid + 128] = g_u[tid + 128];
    s_u[tid + 256] = g_u[tid + 256];

    int base0 = (p * 2 * R + w) * K;
    int base1 = base0 + R * K;

    int ni0 = 0, ni1 = 0, ty0 = 0, ty1 = 0;
    float edt0 = 0.f, edt1 = 0.f;
    if (lane < 16) {
        ni0 = nbr[base0 + lane];
        ni1 = nbr[base1 + lane];
        edt0 = __expf(-dt[base0 + lane]);
        edt1 = __expf(-dt[base1 + lane]);
        ty0 = types[ni0];
        ty1 = types[ni1];
    }
    float es0 = g_es[p * 2];
    float es1 = g_es[p * 2 + 1];
    __syncthreads();                 // s_u staged

    float4 hacc = make_float4(0.f, 0.f, 0.f, 0.f);

#pragma unroll
    for (int s = 0; s < 2; s++) {
        int   ni  = s ? ni1  : ni0;
        int   ty  = s ? ty1  : ty0;
        float edt = s ? edt1 : edt0;
        float es  = s ? es1  : es0;

        float sum = 0.f;
        float4 hs = make_float4(0.f, 0.f, 0.f, 0.f);

#pragma unroll
        for (int b = 0; b < 2; b++) {        // two batches of 8 neighbors
            float4 xv[8];
#pragma unroll
            for (int j = 0; j < 8; j++) {
                int nik = __shfl_sync(0xffffffffu, ni, b * 8 + j);
                xv[j] = *(const float4*)(x + (size_t)nik * D + lane * 4);
            }
#pragma unroll
            for (int j = 0; j < 8; j++) {
                int k = b * 8 + j;
                int tyk = __shfl_sync(0xffffffffu, ty, k);
                const float4 u4 = *(const float4*)&s_u[tyk * D + lane * 4];
                float d = xv[j].x * u4.x + xv[j].y * u4.y +
                          xv[j].z * u4.z + xv[j].w * u4.w;
#pragma unroll
                for (int off = 16; off; off >>= 1)
                    d += __shfl_xor_sync(0xffffffffu, d, off);
                float edtk = __shfl_sync(0xffffffffu, edt, k);
                float ex = __expf((d + es) * edtk);   // same value all lanes
                sum += ex;
                hs.x = fmaf(ex, xv[j].x, hs.x);
                hs.y = fmaf(ex, xv[j].y, hs.y);
                hs.z = fmaf(ex, xv[j].z, hs.z);
                hs.w = fmaf(ex, xv[j].w, hs.w);
            }
        }
        float inv = __fdividef(1.f, sum);
        hacc.x = fmaf(inv, hs.x, hacc.x);
        hacc.y = fmaf(inv, hs.y, hacc.y);
        hacc.z = fmaf(inv, hs.z, hacc.z);
        hacc.w = fmaf(inv, hs.w, hacc.w);
    }

    // store as bf16x2 pair (rounded to bf16 anyway in the MMA)
    uint32_t c0, c1;
    asm("cvt.rn.bf16x2.f32 %0, %1, %2;" : "=r"(c0) : "f"(hacc.y), "f"(hacc.x));
    asm("cvt.rn.bf16x2.f32 %0, %1, %2;" : "=r"(c1) : "f"(hacc.w), "f"(hacc.z));
    *(uint2*)(g_gb + (size_t)(p * R + w) * 64 + lane * 2) = make_uint2(c0, c1);
}

// ---------------------------------------------------------------------------
// Kernel 4: warp-level bf16 tensor-core out-GEMM + fused epilogue, v3.
// out = sigmoid(G @ (0.125*Wb) + bias2)   (0.125 folded into weights).
// 256 CTAs x 256 thr. CTA = 16M x 128N; A (16 KB) staged in smem in
// FRAGMENT order ([kt][lane] uint4 -> one conflict-free LDS.128 per kt,
// shared by all 8 warps). Warp = 16M x 16N; B via 2 LDG.64/kt, unroll x4.
// ~16 warps/SM (vs 7 in the starved v2).
// ---------------------------------------------------------------------------
__global__ __launch_bounds__(256) void mma_out_kernel(float* __restrict__ out) {
    __shared__ __align__(16) uint4 s_a[32 * 32];   // 16 KB

    int tid = threadIdx.x;
    int row0 = blockIdx.x * 16;

    // fill A fragments: idx = kt*32 + lane; 4 items per thread
#pragma unroll
    for (int i = 0; i < 4; i++) {
        int idx = tid + i * 256;
        int kt = idx >> 5;
        int ln = idx & 31;
        int g = ln >> 2, t = ln & 3;
        const uint32_t* gr = g_gb + (size_t)(row0 + g) * 256 + kt * 8 + t;
        uint32_t u0 = gr[0];
        uint32_t u1 = gr[8 * 256];
        uint32_t u2 = gr[4];
        uint32_t u3 = gr[8 * 256 + 4];
        s_a[idx] = make_uint4(u0, u1, u2, u3);
    }
    __syncthreads();

    int w = tid >> 5;
    int lane = tid & 31;
    int g = lane >> 2;
    int t = lane & 3;
    int n0 = w * 16;

    float acc[2][4];
#pragma unroll
    for (int j = 0; j < 2; j++)
#pragma unroll
        for (int i = 0; i < 4; i++) acc[j][i] = 0.f;

#pragma unroll 4
    for (int kt = 0; kt < 32; kt++) {
        uint4 af = s_a[kt * 32 + lane];
        const uint2* brow = g_wbQ + (kt * 4 + t) * 128 + n0 + g;
        uint2 bq0 = __ldg(brow);
        uint2 bq1 = __ldg(brow + 8);
        asm volatile(
            "mma.sync.aligned.m16n8k16.row.col.f32.bf16.bf16.f32 "
            "{%0,%1,%2,%3}, {%4,%5,%6,%7}, {%8,%9}, {%0,%1,%2,%3};"
            : "+f"(acc[0][0]), "+f"(acc[0][1]), "+f"(acc[0][2]), "+f"(acc[0][3])
            : "r"(af.x), "r"(af.y), "r"(af.z), "r"(af.w), "r"(bq0.x), "r"(bq0.y));
        asm volatile(
            "mma.sync.aligned.m16n8k16.row.col.f32.bf16.bf16.f32 "
            "{%0,%1,%2,%3}, {%4,%5,%6,%7}, {%8,%9}, {%0,%1,%2,%3};"
            : "+f"(acc[1][0]), "+f"(acc[1][1]), "+f"(acc[1][2]), "+f"(acc[1][3])
            : "r"(af.x), "r"(af.y), "r"(af.z), "r"(af.w), "r"(bq1.x), "r"(bq1.y));
    }

    // epilogue: bias + sigmoid (scale pre-folded), direct to out
    int rm0 = row0 + g;
    float* orow0 = out + (size_t)rm0 * D;
    float* orow1 = orow0 + 8 * D;
#pragma unroll
    for (int j = 0; j < 2; j++) {
        int nc = n0 + j * 8 + t * 2;
        float b0v = g_bias2[nc];
        float b1v = g_bias2[nc + 1];
        float v00 = acc[j][0] + b0v;
        float v01 = acc[j][1] + b1v;
        float v10 = acc[j][2] + b0v;
        float v11 = acc[j][3] + b1v;
        float2 o0, o1;
        o0.x = __fdividef(1.f, 1.f + __expf(-v00));
        o0.y = __fdividef(1.f, 1.f + __expf(-v01));
        o1.x = __fdividef(1.f, 1.f + __expf(-v10));
        o1.y = __fdividef(1.f, 1.f + __expf(-v11));
        *(float2*)(orow0 + nc) = o0;
        *(float2*)(orow1 + nc) = o1;
    }
}

// ---------------------------------------------------------------------------
// Launch
// ---------------------------------------------------------------------------
extern "C" void kernel_launch(void* const* d_in, const int* in_sizes, int n_in,
                              void* d_out, int out_size) {
    const float* node_embeds   = (const float*)d_in[0];
    const int*   node_pairs    = (const int*)d_in[1];
    const int*   node_type_ids = (const int*)d_in[2];
    const int*   neighbor_idx  = (const int*)d_in[3];
    const float* delta_t       = (const float*)d_in[4];
    const float* W_phi         = (const float*)d_in[5];
    const float* W_zeta        = (const float*)d_in[6];
    const float* W_beta_w      = (const float*)d_in[7];
    const float* W_beta_b      = (const float*)d_in[8];
    float* out = (float*)d_out;

    setup_kernel<<<68, 256>>>(W_phi, W_zeta, W_beta_b, W_beta_w);
    es_kernel<<<(P * 2) / 4, 128>>>(node_embeds, node_pairs, node_type_ids);
    main_kernel<<<P, 128>>>(node_embeds, node_type_ids, neighbor_idx, delta_t);
    mma_out_kernel<<<P / 16, 256>>>(out);
}

// round 16
// speedup vs baseline: 1.4162x; 1.0988x over previous
#include <cuda_runtime.h>
#include <cuda_bf16.h>
#include <cstdint>

// Problem constants
#define NN 200000
#define D  128
#define P  4096
#define R  4
#define T  3
#define K  16

// ---------------------------------------------------------------------------
// Scratch (static __device__ — no runtime allocation)
// ---------------------------------------------------------------------------
__device__ __align__(16) float g_u[T * D];          // u_t = W_phi[t] @ zn
__device__ __align__(16) float g_v[T * D];          // v_t = W_phi[t] @ zs
__device__ __align__(16) float g_bias2[D];          // 0.25 * sum_r W_beta_b[r][e]
__device__ __align__(16) float g_es[P * 2];         // e_s per (p,s)
// G matrix in bf16: row p has 256 uints (512 bf16 = R*D k-values)
__device__ __align__(16) uint32_t g_gb[P * 256];
// Packed bf16 B fragments (0.125*Wb) for m16n8k16: idx = (kt*4+t)*128 + n.
__device__ __align__(16) uint2 g_wbQ[128 * 128];

// ---------------------------------------------------------------------------
// Kernel 1: setup — fused wbq pack (blocks 0..63, with 0.125 prescale),
// u/v prep (64..66), bias2 (67). grid=68 x 256.
// ---------------------------------------------------------------------------
__global__ void setup_kernel(const float* __restrict__ W_phi,
                             const float* __restrict__ W_zeta,
                             const float* __restrict__ W_beta_b,
                             const float* __restrict__ Wb) {
    int b = blockIdx.x;
    int tid = threadIdx.x;
    if (b < 64) {
        int idx = b * 256 + tid;   // row*128 + n
        int row = idx >> 7;        // kt*4 + t
        int n = idx & 127;
        int kt = row >> 2, t = row & 3;
        int k0 = kt * 16 + t * 2;
        float w00 = 0.125f * Wb[k0 * D + n];
        float w01 = 0.125f * Wb[(k0 + 1) * D + n];
        float w10 = 0.125f * Wb[(k0 + 8) * D + n];
        float w11 = 0.125f * Wb[(k0 + 9) * D + n];
        uint32_t b0, b1;
        asm("cvt.rn.bf16x2.f32 %0, %1, %2;" : "=r"(b0) : "f"(w01), "f"(w00));
        asm("cvt.rn.bf16x2.f32 %0, %1, %2;" : "=r"(b1) : "f"(w11), "f"(w10));
        g_wbQ[idx] = make_uint2(b0, b1);
    } else if (b < 67) {
        if (tid < D) {
            int ty = b - 64;
            const float* wrow = W_phi + (ty * D + tid) * D;
            float au = 0.f, av = 0.f;
#pragma unroll 8
            for (int e = 0; e < D; e++) {
                float w = wrow[e];
                au = fmaf(w, W_zeta[e], au);
                av = fmaf(w, W_zeta[D + e], av);
            }
            g_u[ty * D + tid] = au;
            g_v[ty * D + tid] = av;
        }
    } else {
        if (tid < D) {
            float s = 0.f;
#pragma unroll
            for (int r = 0; r < R; r++) s += W_beta_b[r * D + tid];
            g_bias2[tid] = 0.25f * s;
        }
    }
}

// ---------------------------------------------------------------------------
// Kernel 2: e_s per (p,s). One warp per pair-slot. grid=2048 x 128.
// ---------------------------------------------------------------------------
__global__ void es_kernel(const float* __restrict__ x,
                          const int* __restrict__ node_pairs,
                          const int* __restrict__ types) {
    int tid = threadIdx.x;
    int lane = tid & 31;
    int gw = blockIdx.x * 4 + (tid >> 5);   // ps index, 0..8191
    int node = node_pairs[gw];
    int t = types[node];
    const float4 x4 = *(const float4*)(x + (size_t)node * D + lane * 4);
    const float4 v4 = *(const float4*)(g_v + t * D + lane * 4);
    float part = x4.x * v4.x + x4.y * v4.y + x4.z * v4.z + x4.w * v4.w;
#pragma unroll
    for (int off = 16; off; off >>= 1)
        part += __shfl_xor_sync(0xffffffffu, part, off);
    if (lane == 0) g_es[gw] = part;
}

// ---------------------------------------------------------------------------
// Kernel 3: main — gather + softmax + aggregate. Block = pair p (128 thr),
// warp w = relation r. u rows held in REGISTERS (12 floats, T=3) and
// selected by the warp-uniform type via predicated FSEL — no smem at all,
// no barrier; L1tex wavefronts per neighbor halved vs LDS-u (the binding
// pipe at 75.8% in R12). Writes G as bf16.
// ---------------------------------------------------------------------------
__global__ __launch_bounds__(128) void main_kernel(
    const float* __restrict__ x,
    const int* __restrict__ types,
    const int* __restrict__ nbr,
    const float* __restrict__ dt) {

    int p = blockIdx.x;
    int tid = threadIdx.x;
    int w = tid >> 5;       // r
    int lane = tid & 31;

    // all three u rows for this lane's 4 dims: 12 registers
    float4 u_reg0 = *(const float4*)(g_u + lane * 4);
    float4 u_reg1 = *(const float4*)(g_u + D + lane * 4);
    float4 u_reg2 = *(const float4*)(g_u + 2 * D + lane * 4);

    int base0 = (p * 2 * R + w) * K;
    int base1 = base0 + R * K;

    int ni0 = 0, ni1 = 0, ty0 = 0, ty1 = 0;
    float edt0 = 0.f, edt1 = 0.f;
    if (lane < 16) {
        ni0 = nbr[base0 + lane];
        ni1 = nbr[base1 + lane];
        edt0 = __expf(-dt[base0 + lane]);
        edt1 = __expf(-dt[base1 + lane]);
        ty0 = types[ni0];
        ty1 = types[ni1];
    }
    float es0 = g_es[p * 2];
    float es1 = g_es[p * 2 + 1];

    float4 hacc = make_float4(0.f, 0.f, 0.f, 0.f);

#pragma unroll
    for (int s = 0; s < 2; s++) {
        int   ni  = s ? ni1  : ni0;
        int   ty  = s ? ty1  : ty0;
        float edt = s ? edt1 : edt0;
        float es  = s ? es1  : es0;

        float sum = 0.f;
        float4 hs = make_float4(0.f, 0.f, 0.f, 0.f);

#pragma unroll
        for (int b = 0; b < 2; b++) {        // two batches of 8 neighbors
            float4 xv[8];
#pragma unroll
            for (int j = 0; j < 8; j++) {
                int nik = __shfl_sync(0xffffffffu, ni, b * 8 + j);
                xv[j] = *(const float4*)(x + (size_t)nik * D + lane * 4);
            }
#pragma unroll
            for (int j = 0; j < 8; j++) {
                int k = b * 8 + j;
                int tyk = __shfl_sync(0xffffffffu, ty, k);
                // register select (tyk is warp-uniform): 2 FSEL chains
                float4 u4 = u_reg0;
                if (tyk == 1) u4 = u_reg1;
                if (tyk == 2) u4 = u_reg2;
                float d = xv[j].x * u4.x + xv[j].y * u4.y +
                          xv[j].z * u4.z + xv[j].w * u4.w;
#pragma unroll
                for (int off = 16; off; off >>= 1)
                    d += __shfl_xor_sync(0xffffffffu, d, off);
                float edtk = __shfl_sync(0xffffffffu, edt, k);
                float ex = __expf((d + es) * edtk);   // same value all lanes
                sum += ex;
                hs.x = fmaf(ex, xv[j].x, hs.x);
                hs.y = fmaf(ex, xv[j].y, hs.y);
                hs.z = fmaf(ex, xv[j].z, hs.z);
                hs.w = fmaf(ex, xv[j].w, hs.w);
            }
        }
        float inv = __fdividef(1.f, sum);
        hacc.x = fmaf(inv, hs.x, hacc.x);
        hacc.y = fmaf(inv, hs.y, hacc.y);
        hacc.z = fmaf(inv, hs.z, hacc.z);
        hacc.w = fmaf(inv, hs.w, hacc.w);
    }

    // store as bf16x2 pair (rounded to bf16 anyway in the MMA)
    uint32_t c0, c1;
    asm("cvt.rn.bf16x2.f32 %0, %1, %2;" : "=r"(c0) : "f"(hacc.y), "f"(hacc.x));
    asm("cvt.rn.bf16x2.f32 %0, %1, %2;" : "=r"(c1) : "f"(hacc.w), "f"(hacc.z));
    *(uint2*)(g_gb + (size_t)(p * R + w) * 64 + lane * 2) = make_uint2(c0, c1);
}

// ---------------------------------------------------------------------------
// Kernel 4: warp-level bf16 tensor-core out-GEMM + fused epilogue, v4.
// out = sigmoid(G @ (0.125*Wb) + bias2).
// 256 CTAs x 256 thr. CTA = 16M x 128N. A staged via COALESCED LDG.128
// (4/thread) into padded raw-order smem (pad 268 words -> in-loop 4xLDS.32
// fragment reads are conflict-free: (g*12+t) mod 32 covers all banks).
// Warp = 16M x 16N; B software-pipelined: kt+1's uint2 pair prefetched
// before kt's MMAs issue, hiding L2 latency behind tensor work.
// ---------------------------------------------------------------------------
#define APAD 268

__global__ __launch_bounds__(256) void mma_out_kernel(float* __restrict__ out) {
    __shared__ __align__(16) uint32_t s_a[16 * APAD];   // 16.75 KB

    int tid = threadIdx.x;
    int row0 = blockIdx.x * 16;

    // coalesced A fill: 1024 uint4 (16 rows x 64 uint4), 4 per thread
    const uint4* gsrc = (const uint4*)(g_gb + (size_t)row0 * 256);
#pragma unroll
    for (int i = 0; i < 4; i++) {
        int idx = tid + i * 256;          // uint4 index
        uint4 v = gsrc[idx];
        int row = idx >> 6;
        int c = (idx & 63) * 4;
        *(uint4*)(s_a + row * APAD + c) = v;   // APAD%4==0 -> 16B aligned
    }
    __syncthreads();

    int w = tid >> 5;
    int lane = tid & 31;
    int g = lane >> 2;
    int t = lane & 3;
    int n0 = w * 16;

    const uint32_t* arow0 = s_a + g * APAD + t;
    const uint32_t* arow1 = s_a + (g + 8) * APAD + t;
    const uint2* bbase = g_wbQ + t * 128 + n0 + g;    // + kt*512

    float acc[2][4];
#pragma unroll
    for (int j = 0; j < 2; j++)
#pragma unroll
        for (int i = 0; i < 4; i++) acc[j][i] = 0.f;

    uint2 bq0 = __ldg(bbase);
    uint2 bq1 = __ldg(bbase + 8);

#pragma unroll
    for (int kt = 0; kt < 32; kt++) {
        uint2 nb0, nb1;
        if (kt < 31) {                    // prefetch next B pair
            nb0 = __ldg(bbase + (kt + 1) * 512);
            nb1 = __ldg(bbase + (kt + 1) * 512 + 8);
        }
        uint32_t a0 = arow0[kt * 8];
        uint32_t a1 = arow1[kt * 8];
        uint32_t a2 = arow0[kt * 8 + 4];
        uint32_t a3 = arow1[kt * 8 + 4];
        asm volatile(
            "mma.sync.aligned.m16n8k16.row.col.f32.bf16.bf16.f32 "
            "{%0,%1,%2,%3}, {%4,%5,%6,%7}, {%8,%9}, {%0,%1,%2,%3};"
            : "+f"(acc[0][0]), "+f"(acc[0][1]), "+f"(acc[0][2]), "+f"(acc[0][3])
            : "r"(a0), "r"(a1), "r"(a2), "r"(a3), "r"(bq0.x), "r"(bq0.y));
        asm volatile(
            "mma.sync.aligned.m16n8k16.row.col.f32.bf16.bf16.f32 "
            "{%0,%1,%2,%3}, {%4,%5,%6,%7}, {%8,%9}, {%0,%1,%2,%3};"
            : "+f"(acc[1][0]), "+f"(acc[1][1]), "+f"(acc[1][2]), "+f"(acc[1][3])
            : "r"(a0), "r"(a1), "r"(a2), "r"(a3), "r"(bq1.x), "r"(bq1.y));
        bq0 = nb0;
        bq1 = nb1;
    }

    // epilogue: bias + sigmoid (0.125 pre-folded into weights)
    int rm0 = row0 + g;
    float* orow0 = out + (size_t)rm0 * D;
    float* orow1 = orow0 + 8 * D;
#pragma unroll
    for (int j = 0; j < 2; j++) {
        int nc = n0 + j * 8 + t * 2;
        float b0v = g_bias2[nc];
        float b1v = g_bias2[nc + 1];
        float v00 = acc[j][0] + b0v;
        float v01 = acc[j][1] + b1v;
        float v10 = acc[j][2] + b0v;
        float v11 = acc[j][3] + b1v;
        float2 o0, o1;
        o0.x = __fdividef(1.f, 1.f + __expf(-v00));
        o0.y = __fdividef(1.f, 1.f + __expf(-v01));
        o1.x = __fdividef(1.f, 1.f + __expf(-v10));
        o1.y = __fdividef(1.f, 1.f + __expf(-v11));
        *(float2*)(orow0 + nc) = o0;
        *(float2*)(orow1 + nc) = o1;
    }
}

// ---------------------------------------------------------------------------
// Launch
// ---------------------------------------------------------------------------
extern "C" void kernel_launch(void* const* d_in, const int* in_sizes, int n_in,
                              void* d_out, int out_size) {
    const float* node_embeds   = (const float*)d_in[0];
    const int*   node_pairs    = (const int*)d_in[1];
    const int*   node_type_ids = (const int*)d_in[2];
    const int*   neighbor_idx  = (const int*)d_in[3];
    const float* delta_t       = (const float*)d_in[4];
    const float* W_phi         = (const float*)d_in[5];
    const float* W_zeta        = (const float*)d_in[6];
    const float* W_beta_w      = (const float*)d_in[7];
    const float* W_beta_b      = (const float*)d_in[8];
    float* out = (float*)d_out;

    setup_kernel<<<68, 256>>>(W_phi, W_zeta, W_beta_b, W_beta_w);
    es_kernel<<<(P * 2) / 4, 128>>>(node_embeds, node_pairs, node_type_ids);
    main_kernel<<<P, 128>>>(node_embeds, node_type_ids, neighbor_idx, delta_t);
    mma_out_kernel<<<P / 16, 256>>>(out);
}